// round 1
// baseline (speedup 1.0000x reference)
#include <cuda_runtime.h>
#include <math.h>

#define BATCH   2
#define SEQ     2048
#define DMODEL  1024
#define NHEADS  16
#define DK      64
#define NQ      (BATCH * SEQ)   // 4096 rows

// Scratch (allocation-free: device globals)
__device__ float g_q[BATCH * NHEADS * SEQ * DK];   // [b][h][s][d]
__device__ float g_k[BATCH * NHEADS * SEQ * DK];
__device__ float g_v[BATCH * NHEADS * SEQ * DK];
__device__ float g_ctx[NQ * DMODEL];               // [b*S+s][h*64+d]

// ---------------------------------------------------------------------------
// Kernel 1: fused QKV projection (C = x @ W^T for Wq,Wk,Wv) + RoPE epilogue.
// Tile 64x64, BK=16, 256 threads, 4x4 per thread per output.
// ---------------------------------------------------------------------------
__global__ __launch_bounds__(256) void qkv_rope_kernel(
    const float* __restrict__ x,
    const float* __restrict__ Wq,
    const float* __restrict__ Wk,
    const float* __restrict__ Wv)
{
    __shared__ float As[16][65];
    __shared__ float Bqs[16][65];
    __shared__ float Bks[16][65];
    __shared__ float Bvs[16][65];

    const int tx = threadIdx.x;          // 0..15
    const int ty = threadIdx.y;          // 0..15
    const int tid = ty * 16 + tx;        // 0..255
    const int m0 = blockIdx.y * 64;      // row tile (token)
    const int n0 = blockIdx.x * 64;      // col tile (output feature)

    const int lr = tid >> 2;             // 0..63  row within tile to load
    const int lk = (tid & 3) * 4;        // 0,4,8,12  k-offset (float4)

    float aq[4][4] = {{0.f}}, ak[4][4] = {{0.f}}, av[4][4] = {{0.f}};

    for (int k0 = 0; k0 < DMODEL; k0 += 16) {
        float4 va = *(const float4*)&x  [(m0 + lr) * DMODEL + k0 + lk];
        float4 vq = *(const float4*)&Wq [(n0 + lr) * DMODEL + k0 + lk];
        float4 vk = *(const float4*)&Wk [(n0 + lr) * DMODEL + k0 + lk];
        float4 vv = *(const float4*)&Wv [(n0 + lr) * DMODEL + k0 + lk];
        __syncthreads();
        As [lk + 0][lr] = va.x; As [lk + 1][lr] = va.y; As [lk + 2][lr] = va.z; As [lk + 3][lr] = va.w;
        Bqs[lk + 0][lr] = vq.x; Bqs[lk + 1][lr] = vq.y; Bqs[lk + 2][lr] = vq.z; Bqs[lk + 3][lr] = vq.w;
        Bks[lk + 0][lr] = vk.x; Bks[lk + 1][lr] = vk.y; Bks[lk + 2][lr] = vk.z; Bks[lk + 3][lr] = vk.w;
        Bvs[lk + 0][lr] = vv.x; Bvs[lk + 1][lr] = vv.y; Bvs[lk + 2][lr] = vv.z; Bvs[lk + 3][lr] = vv.w;
        __syncthreads();

        #pragma unroll
        for (int k = 0; k < 16; k++) {
            float a[4], bq[4], bk[4], bv[4];
            #pragma unroll
            for (int i = 0; i < 4; i++) a[i] = As[k][ty * 4 + i];
            #pragma unroll
            for (int j = 0; j < 4; j++) {
                bq[j] = Bqs[k][tx * 4 + j];
                bk[j] = Bks[k][tx * 4 + j];
                bv[j] = Bvs[k][tx * 4 + j];
            }
            #pragma unroll
            for (int i = 0; i < 4; i++)
                #pragma unroll
                for (int j = 0; j < 4; j++) {
                    aq[i][j] += a[i] * bq[j];
                    ak[i][j] += a[i] * bk[j];
                    av[i][j] += a[i] * bv[j];
                }
        }
    }

    // Epilogue: RoPE for q,k; plain store for v. Layout [b][h][s][d].
    #pragma unroll
    for (int i = 0; i < 4; i++) {
        const int row = m0 + ty * 4 + i;       // global token index
        const int bb = row / SEQ;
        const int s  = row - bb * SEQ;
        #pragma unroll
        for (int jp = 0; jp < 4; jp += 2) {
            const int col = n0 + tx * 4 + jp;  // even feature index
            const int h   = col >> 6;
            const int dd  = col & 63;          // even
            // inv_freq = THETA^(-dd/64); accurate powf/sincosf keep phase err << 1e-3
            float freq = powf(10000.0f, -(float)dd * (1.0f / 64.0f));
            float ang  = (float)s * freq;
            float sn, cs;
            sincosf(ang, &sn, &cs);
            const int base = ((bb * NHEADS + h) * SEQ + s) * DK + dd;
            float q1 = aq[i][jp], q2 = aq[i][jp + 1];
            float k1 = ak[i][jp], k2 = ak[i][jp + 1];
            g_q[base]     = q1 * cs - q2 * sn;
            g_q[base + 1] = q1 * sn + q2 * cs;
            g_k[base]     = k1 * cs - k2 * sn;
            g_k[base + 1] = k1 * sn + k2 * cs;
            g_v[base]     = av[i][jp];
            g_v[base + 1] = av[i][jp + 1];
        }
    }
}

// ---------------------------------------------------------------------------
// Kernel 2: fused causal attention, flash style.
// Grid (S/128, H, B); 128 threads; one query per thread; 64-key SMEM tiles.
// Online softmax in chunks of 16 keys (amortizes acc rescale).
// ---------------------------------------------------------------------------
__global__ __launch_bounds__(128) void attn_kernel()
{
    __shared__ float4 Ks[64 * 16];   // 64 keys x 64 floats
    __shared__ float4 Vs[64 * 16];

    const int tid = threadIdx.x;
    const int h = blockIdx.y;
    const int b = blockIdx.z;
    const int q = blockIdx.x * 128 + tid;

    const int seq_base = (b * NHEADS + h) * SEQ;            // in keys
    const float4* kp = (const float4*)g_k + seq_base * 16;  // 16 float4 per key
    const float4* vp = (const float4*)g_v + seq_base * 16;

    float4 qr[16];
    {
        const float4* qp = (const float4*)g_q + (seq_base + q) * 16;
        #pragma unroll
        for (int i = 0; i < 16; i++) qr[i] = qp[i];
    }

    float m = -1e30f, l = 0.f;
    float4 acc[16];
    #pragma unroll
    for (int i = 0; i < 16; i++) acc[i] = make_float4(0.f, 0.f, 0.f, 0.f);

    const int nk = blockIdx.x * 128 + 128;   // keys needed by this CTA

    for (int kt = 0; kt < nk; kt += 64) {
        __syncthreads();
        #pragma unroll
        for (int i = 0; i < 8; i++) {
            Ks[i * 128 + tid] = kp[kt * 16 + i * 128 + tid];
            Vs[i * 128 + tid] = vp[kt * 16 + i * 128 + tid];
        }
        __syncthreads();

        const int jmax = q - kt + 1;   // #valid keys in this tile (may be <=0 or >64)

        for (int jc = 0; jc < 64; jc += 16) {
            if (jc >= jmax) break;     // whole chunk masked for this thread

            float sc[16];
            float cmax = -1e30f;
            #pragma unroll
            for (int j = 0; j < 16; j++) {
                const float4* kr = &Ks[(jc + j) * 16];
                float s = 0.f;
                #pragma unroll
                for (int d = 0; d < 16; d++) {
                    float4 kv = kr[d];
                    s += qr[d].x * kv.x + qr[d].y * kv.y + qr[d].z * kv.z + qr[d].w * kv.w;
                }
                s *= 0.125f;                       // 1/sqrt(64)
                if (jc + j >= jmax) s = -1e30f;    // causal mask
                sc[j] = s;
                cmax = fmaxf(cmax, s);
            }

            float newm = fmaxf(m, cmax);
            float alpha = __expf(m - newm);
            m = newm;
            l *= alpha;
            #pragma unroll
            for (int d = 0; d < 16; d++) {
                acc[d].x *= alpha; acc[d].y *= alpha;
                acc[d].z *= alpha; acc[d].w *= alpha;
            }
            #pragma unroll
            for (int j = 0; j < 16; j++) {
                float p = __expf(sc[j] - m);
                l += p;
                const float4* vr = &Vs[(jc + j) * 16];
                #pragma unroll
                for (int d = 0; d < 16; d++) {
                    float4 vv = vr[d];
                    acc[d].x += p * vv.x; acc[d].y += p * vv.y;
                    acc[d].z += p * vv.z; acc[d].w += p * vv.w;
                }
            }
        }
    }

    const float inv_l = 1.0f / l;
    float4* op = (float4*)(g_ctx + (b * SEQ + q) * DMODEL + h * DK);
    #pragma unroll
    for (int d = 0; d < 16; d++) {
        float4 o = acc[d];
        o.x *= inv_l; o.y *= inv_l; o.z *= inv_l; o.w *= inv_l;
        op[d] = o;
    }
}

// ---------------------------------------------------------------------------
// Kernel 3: output projection out = ctx @ Wo^T. Same 64x64x16 tiling.
// ---------------------------------------------------------------------------
__global__ __launch_bounds__(256) void oproj_kernel(
    const float* __restrict__ Wo, float* __restrict__ out)
{
    __shared__ float As[16][65];
    __shared__ float Bs[16][65];

    const int tx = threadIdx.x, ty = threadIdx.y;
    const int tid = ty * 16 + tx;
    const int m0 = blockIdx.y * 64;
    const int n0 = blockIdx.x * 64;

    const int lr = tid >> 2;
    const int lk = (tid & 3) * 4;

    float acc[4][4] = {{0.f}};

    for (int k0 = 0; k0 < DMODEL; k0 += 16) {
        float4 va = *(const float4*)&g_ctx[(m0 + lr) * DMODEL + k0 + lk];
        float4 vb = *(const float4*)&Wo   [(n0 + lr) * DMODEL + k0 + lk];
        __syncthreads();
        As[lk + 0][lr] = va.x; As[lk + 1][lr] = va.y; As[lk + 2][lr] = va.z; As[lk + 3][lr] = va.w;
        Bs[lk + 0][lr] = vb.x; Bs[lk + 1][lr] = vb.y; Bs[lk + 2][lr] = vb.z; Bs[lk + 3][lr] = vb.w;
        __syncthreads();

        #pragma unroll
        for (int k = 0; k < 16; k++) {
            float a[4], bb[4];
            #pragma unroll
            for (int i = 0; i < 4; i++) a[i] = As[k][ty * 4 + i];
            #pragma unroll
            for (int j = 0; j < 4; j++) bb[j] = Bs[k][tx * 4 + j];
            #pragma unroll
            for (int i = 0; i < 4; i++)
                #pragma unroll
                for (int j = 0; j < 4; j++)
                    acc[i][j] += a[i] * bb[j];
        }
    }

    #pragma unroll
    for (int i = 0; i < 4; i++) {
        const int row = m0 + ty * 4 + i;
        #pragma unroll
        for (int j = 0; j < 4; j++) {
            const int col = n0 + tx * 4 + j;
            out[row * DMODEL + col] = acc[i][j];
        }
    }
}

// ---------------------------------------------------------------------------
extern "C" void kernel_launch(void* const* d_in, const int* in_sizes, int n_in,
                              void* d_out, int out_size)
{
    const float* x  = (const float*)d_in[0];
    const float* Wq = (const float*)d_in[1];
    const float* Wk = (const float*)d_in[2];
    const float* Wv = (const float*)d_in[3];
    const float* Wo = (const float*)d_in[4];
    float* out = (float*)d_out;

    dim3 gp(DMODEL / 64, NQ / 64);
    dim3 bp(16, 16);
    qkv_rope_kernel<<<gp, bp>>>(x, Wq, Wk, Wv);

    dim3 ga(SEQ / 128, NHEADS, BATCH);
    attn_kernel<<<ga, 128>>>();

    oproj_kernel<<<gp, bp>>>(Wo, out);
}

// round 2
// speedup vs baseline: 1.4795x; 1.4795x over previous
#include <cuda_runtime.h>
#include <math.h>

#define BATCH   2
#define SEQ     2048
#define DMODEL  1024
#define NHEADS  16
#define DK      64
#define NQ      (BATCH * SEQ)   // 4096 rows
#define GK      DMODEL          // GEMM K dim (all 4 projections)

// Scratch (allocation-free: device globals)
__device__ float g_q[BATCH * NHEADS * SEQ * DK];   // [b][h][s][d]
__device__ float g_k[BATCH * NHEADS * SEQ * DK];
__device__ float g_v[BATCH * NHEADS * SEQ * DK];
__device__ float g_ctx[NQ * DMODEL];               // [b*S+s][h*64+d]
__device__ float g_cos[SEQ * 32];                  // rope table [s][d/2]
__device__ float g_sin[SEQ * 32];

// ---------------------------------------------------------------------------
// RoPE table: accurate powf/sincosf once, consumed by GEMM epilogues.
// ---------------------------------------------------------------------------
__global__ void rope_table_kernel()
{
    int i = blockIdx.x * 256 + threadIdx.x;   // SEQ*32 = 65536
    int s = i >> 5;
    int j = i & 31;
    float freq = powf(10000.0f, -(float)(2 * j) * (1.0f / 64.0f));
    float sn, cs;
    sincosf((float)s * freq, &sn, &cs);
    g_cos[i] = cs;
    g_sin[i] = sn;
}

// ---------------------------------------------------------------------------
// tf32 tensor-core GEMM: C[M,N] = A[M,K] @ W[N,K]^T
// CTA tile 128x128, 8 warps (2m x 4n), warp tile 64x32, BK=16 double-buffered.
// EPI: 0 = RoPE scatter (q/k), 1 = plain scatter (v), 2 = row-major store (out)
// ---------------------------------------------------------------------------
#define BM  128
#define BN  128
#define BKK 16
#define LDP 20    // smem row pitch in words (16 + 4 pad -> conflict-free frags)

__device__ __forceinline__ unsigned f2tf(float f)
{
    unsigned u;
    asm("cvt.rna.tf32.f32 %0, %1;" : "=r"(u) : "f"(f));
    return u;
}

__device__ __forceinline__ void mma_tf32(float* d, const unsigned* a, const unsigned* b)
{
    asm volatile(
        "mma.sync.aligned.m16n8k8.row.col.f32.tf32.tf32.f32 "
        "{%0,%1,%2,%3},{%4,%5,%6,%7},{%8,%9},{%0,%1,%2,%3};"
        : "+f"(d[0]), "+f"(d[1]), "+f"(d[2]), "+f"(d[3])
        : "r"(a[0]), "r"(a[1]), "r"(a[2]), "r"(a[3]), "r"(b[0]), "r"(b[1]));
}

__device__ __forceinline__ void sts_tile(unsigned* Abuf, unsigned* Bbuf,
                                         int row0, int kc,
                                         float4 a0, float4 a1,
                                         float4 b0, float4 b1)
{
    uint4 t;
    unsigned* p = Abuf + row0 * LDP + kc;
    t.x = f2tf(a0.x); t.y = f2tf(a0.y); t.z = f2tf(a0.z); t.w = f2tf(a0.w);
    *(uint4*)p = t;
    t.x = f2tf(a1.x); t.y = f2tf(a1.y); t.z = f2tf(a1.z); t.w = f2tf(a1.w);
    *(uint4*)(p + 64 * LDP) = t;
    p = Bbuf + row0 * LDP + kc;
    t.x = f2tf(b0.x); t.y = f2tf(b0.y); t.z = f2tf(b0.z); t.w = f2tf(b0.w);
    *(uint4*)p = t;
    t.x = f2tf(b1.x); t.y = f2tf(b1.y); t.z = f2tf(b1.z); t.w = f2tf(b1.w);
    *(uint4*)(p + 64 * LDP) = t;
}

template <int EPI>
__global__ __launch_bounds__(256) void gemm_kernel(
    const float* __restrict__ A,
    const float* __restrict__ W,
    float* __restrict__ dst)
{
    __shared__ __align__(16) unsigned As[2][BM * LDP];
    __shared__ __align__(16) unsigned Bs[2][BN * LDP];

    const int tid  = threadIdx.x;
    const int lane = tid & 31;
    const int warp = tid >> 5;
    const int wm   = warp & 1;    // 0..1
    const int wn   = warp >> 1;   // 0..3
    const int m0   = blockIdx.y * BM;
    const int n0   = blockIdx.x * BN;

    const int lr = lane >> 2;     // 0..7
    const int lc = lane & 3;      // 0..3

    const int row0 = tid >> 2;           // 0..63
    const int kc   = (tid & 3) * 4;      // 0,4,8,12

    const float* Aptr = A + (m0 + row0) * GK + kc;
    const float* Wptr = W + (n0 + row0) * GK + kc;

    float c[4][4][4];
    #pragma unroll
    for (int i = 0; i < 4; i++)
        #pragma unroll
        for (int j = 0; j < 4; j++)
            #pragma unroll
            for (int r = 0; r < 4; r++)
                c[i][j][r] = 0.f;

    const int NST = GK / BKK;   // 64 stages

    float4 la0 = *(const float4*)Aptr;
    float4 la1 = *(const float4*)(Aptr + 64 * GK);
    float4 lb0 = *(const float4*)Wptr;
    float4 lb1 = *(const float4*)(Wptr + 64 * GK);
    sts_tile(As[0], Bs[0], row0, kc, la0, la1, lb0, lb1);
    __syncthreads();

    for (int s = 0; s < NST; s++) {
        const int cur = s & 1;
        if (s + 1 < NST) {
            const float* ap = Aptr + (s + 1) * BKK;
            const float* wp = Wptr + (s + 1) * BKK;
            la0 = *(const float4*)ap;
            la1 = *(const float4*)(ap + 64 * GK);
            lb0 = *(const float4*)wp;
            lb1 = *(const float4*)(wp + 64 * GK);
        }

        #pragma unroll
        for (int ks = 0; ks < 2; ks++) {
            unsigned af[4][4], bf[4][2];
            #pragma unroll
            for (int mf = 0; mf < 4; mf++) {
                const int m = wm * 64 + mf * 16 + lr;
                const unsigned* p = &As[cur][m * LDP + ks * 8 + lc];
                af[mf][0] = p[0];
                af[mf][1] = p[8 * LDP];
                af[mf][2] = p[4];
                af[mf][3] = p[8 * LDP + 4];
            }
            #pragma unroll
            for (int nf = 0; nf < 4; nf++) {
                const int n = wn * 32 + nf * 8 + lr;
                const unsigned* p = &Bs[cur][n * LDP + ks * 8 + lc];
                bf[nf][0] = p[0];
                bf[nf][1] = p[4];
            }
            #pragma unroll
            for (int mf = 0; mf < 4; mf++)
                #pragma unroll
                for (int nf = 0; nf < 4; nf++)
                    mma_tf32(c[mf][nf], af[mf], bf[nf]);
        }

        if (s + 1 < NST) {
            sts_tile(As[(s + 1) & 1], Bs[(s + 1) & 1], row0, kc, la0, la1, lb0, lb1);
            __syncthreads();
        }
    }

    // Epilogue
    #pragma unroll
    for (int mf = 0; mf < 4; mf++) {
        #pragma unroll
        for (int nf = 0; nf < 4; nf++) {
            const int col = n0 + wn * 32 + nf * 8 + lc * 2;   // even
            #pragma unroll
            for (int half = 0; half < 2; half++) {
                const int r  = m0 + wm * 64 + mf * 16 + lr + half * 8;
                const float v0 = c[mf][nf][half * 2 + 0];
                const float v1 = c[mf][nf][half * 2 + 1];
                if (EPI == 2) {
                    *(float2*)&dst[r * DMODEL + col] = make_float2(v0, v1);
                } else {
                    const int bb = r >> 11;            // / SEQ
                    const int sI = r & (SEQ - 1);
                    const int h  = col >> 6;
                    const int dd = col & 63;           // even
                    const int base = ((bb * NHEADS + h) * SEQ + sI) * DK + dd;
                    if (EPI == 0) {
                        const float cs = g_cos[sI * 32 + (dd >> 1)];
                        const float sn = g_sin[sI * 32 + (dd >> 1)];
                        *(float2*)&dst[base] =
                            make_float2(v0 * cs - v1 * sn, v0 * sn + v1 * cs);
                    } else {
                        *(float2*)&dst[base] = make_float2(v0, v1);
                    }
                }
            }
        }
    }
}

// ---------------------------------------------------------------------------
// Kernel 2: fused causal attention, flash style (unchanged from R0).
// Grid (S/128, H, B); 128 threads; one query per thread; 64-key SMEM tiles.
// ---------------------------------------------------------------------------
__global__ __launch_bounds__(128) void attn_kernel()
{
    __shared__ float4 Ks[64 * 16];   // 64 keys x 64 floats
    __shared__ float4 Vs[64 * 16];

    const int tid = threadIdx.x;
    const int h = blockIdx.y;
    const int b = blockIdx.z;
    const int q = blockIdx.x * 128 + tid;

    const int seq_base = (b * NHEADS + h) * SEQ;
    const float4* kp = (const float4*)g_k + seq_base * 16;
    const float4* vp = (const float4*)g_v + seq_base * 16;

    float4 qr[16];
    {
        const float4* qp = (const float4*)g_q + (seq_base + q) * 16;
        #pragma unroll
        for (int i = 0; i < 16; i++) qr[i] = qp[i];
    }

    float m = -1e30f, l = 0.f;
    float4 acc[16];
    #pragma unroll
    for (int i = 0; i < 16; i++) acc[i] = make_float4(0.f, 0.f, 0.f, 0.f);

    const int nk = blockIdx.x * 128 + 128;

    for (int kt = 0; kt < nk; kt += 64) {
        __syncthreads();
        #pragma unroll
        for (int i = 0; i < 8; i++) {
            Ks[i * 128 + tid] = kp[kt * 16 + i * 128 + tid];
            Vs[i * 128 + tid] = vp[kt * 16 + i * 128 + tid];
        }
        __syncthreads();

        const int jmax = q - kt + 1;

        for (int jc = 0; jc < 64; jc += 16) {
            if (jc >= jmax) break;

            float sc[16];
            float cmax = -1e30f;
            #pragma unroll
            for (int j = 0; j < 16; j++) {
                const float4* kr = &Ks[(jc + j) * 16];
                float s = 0.f;
                #pragma unroll
                for (int d = 0; d < 16; d++) {
                    float4 kv = kr[d];
                    s += qr[d].x * kv.x + qr[d].y * kv.y + qr[d].z * kv.z + qr[d].w * kv.w;
                }
                s *= 0.125f;
                if (jc + j >= jmax) s = -1e30f;
                sc[j] = s;
                cmax = fmaxf(cmax, s);
            }

            float newm = fmaxf(m, cmax);
            float alpha = __expf(m - newm);
            m = newm;
            l *= alpha;
            #pragma unroll
            for (int d = 0; d < 16; d++) {
                acc[d].x *= alpha; acc[d].y *= alpha;
                acc[d].z *= alpha; acc[d].w *= alpha;
            }
            #pragma unroll
            for (int j = 0; j < 16; j++) {
                float p = __expf(sc[j] - m);
                l += p;
                const float4* vr = &Vs[(jc + j) * 16];
                #pragma unroll
                for (int d = 0; d < 16; d++) {
                    float4 vv = vr[d];
                    acc[d].x += p * vv.x; acc[d].y += p * vv.y;
                    acc[d].z += p * vv.z; acc[d].w += p * vv.w;
                }
            }
        }
    }

    const float inv_l = 1.0f / l;
    float4* op = (float4*)(g_ctx + (b * SEQ + q) * DMODEL + h * DK);
    #pragma unroll
    for (int d = 0; d < 16; d++) {
        float4 o = acc[d];
        o.x *= inv_l; o.y *= inv_l; o.z *= inv_l; o.w *= inv_l;
        op[d] = o;
    }
}

// ---------------------------------------------------------------------------
extern "C" void kernel_launch(void* const* d_in, const int* in_sizes, int n_in,
                              void* d_out, int out_size)
{
    const float* x  = (const float*)d_in[0];
    const float* Wq = (const float*)d_in[1];
    const float* Wk = (const float*)d_in[2];
    const float* Wv = (const float*)d_in[3];
    const float* Wo = (const float*)d_in[4];
    float* out = (float*)d_out;

    float* q_p;   cudaGetSymbolAddress((void**)&q_p,   g_q);
    float* k_p;   cudaGetSymbolAddress((void**)&k_p,   g_k);
    float* v_p;   cudaGetSymbolAddress((void**)&v_p,   g_v);
    float* ctx_p; cudaGetSymbolAddress((void**)&ctx_p, g_ctx);

    rope_table_kernel<<<256, 256>>>();

    dim3 gg(DMODEL / BN, NQ / BM);
    gemm_kernel<0><<<gg, 256>>>(x, Wq, q_p);
    gemm_kernel<0><<<gg, 256>>>(x, Wk, k_p);
    gemm_kernel<1><<<gg, 256>>>(x, Wv, v_p);

    dim3 ga(SEQ / 128, NHEADS, BATCH);
    attn_kernel<<<ga, 128>>>();

    gemm_kernel<2><<<gg, 256>>>(ctx_p, Wo, out);
}

// round 3
// speedup vs baseline: 3.5996x; 2.4330x over previous
#include <cuda_runtime.h>
#include <math.h>

#define BATCH   2
#define SEQ     2048
#define DMODEL  1024
#define NHEADS  16
#define DK      64
#define NQ      (BATCH * SEQ)   // 4096 rows
#define GK      DMODEL          // GEMM K dim (all 4 projections)

// Scratch (allocation-free: device globals)
__device__ float g_q[BATCH * NHEADS * SEQ * DK];   // [b][h][s][d]
__device__ float g_k[BATCH * NHEADS * SEQ * DK];
__device__ float g_v[BATCH * NHEADS * SEQ * DK];
__device__ float g_ctx[NQ * DMODEL];               // [b*S+s][h*64+d]
__device__ float g_cos[SEQ * 32];                  // rope table [s][d/2]
__device__ float g_sin[SEQ * 32];

// ---------------------------------------------------------------------------
// RoPE table: accurate powf/sincosf once, consumed by GEMM epilogues.
// ---------------------------------------------------------------------------
__global__ void rope_table_kernel()
{
    int i = blockIdx.x * 256 + threadIdx.x;   // SEQ*32 = 65536
    int s = i >> 5;
    int j = i & 31;
    float freq = powf(10000.0f, -(float)(2 * j) * (1.0f / 64.0f));
    float sn, cs;
    sincosf((float)s * freq, &sn, &cs);
    g_cos[i] = cs;
    g_sin[i] = sn;
}

// ---------------------------------------------------------------------------
// Shared tf32 helpers
// ---------------------------------------------------------------------------
__device__ __forceinline__ unsigned f2tf(float f)
{
    unsigned u;
    asm("cvt.rna.tf32.f32 %0, %1;" : "=r"(u) : "f"(f));
    return u;
}

__device__ __forceinline__ void mma_tf32(float* d, const unsigned* a, const unsigned* b)
{
    asm volatile(
        "mma.sync.aligned.m16n8k8.row.col.f32.tf32.tf32.f32 "
        "{%0,%1,%2,%3},{%4,%5,%6,%7},{%8,%9},{%0,%1,%2,%3};"
        : "+f"(d[0]), "+f"(d[1]), "+f"(d[2]), "+f"(d[3])
        : "r"(a[0]), "r"(a[1]), "r"(a[2]), "r"(a[3]), "r"(b[0]), "r"(b[1]));
}

// ---------------------------------------------------------------------------
// tf32 tensor-core GEMM: C[M,N] = A[M,K] @ W[N,K]^T
// CTA tile 128x128, 8 warps (2m x 4n), warp tile 64x32, BK=16 double-buffered.
// EPI: 0 = RoPE scatter (q/k), 1 = plain scatter (v), 2 = row-major store (out)
// ---------------------------------------------------------------------------
#define BM  128
#define BN  128
#define BKK 16
#define LDP 20    // smem row pitch in words (16 + 4 pad -> conflict-free frags)

__device__ __forceinline__ void sts_tile(unsigned* Abuf, unsigned* Bbuf,
                                         int row0, int kc,
                                         float4 a0, float4 a1,
                                         float4 b0, float4 b1)
{
    uint4 t;
    unsigned* p = Abuf + row0 * LDP + kc;
    t.x = f2tf(a0.x); t.y = f2tf(a0.y); t.z = f2tf(a0.z); t.w = f2tf(a0.w);
    *(uint4*)p = t;
    t.x = f2tf(a1.x); t.y = f2tf(a1.y); t.z = f2tf(a1.z); t.w = f2tf(a1.w);
    *(uint4*)(p + 64 * LDP) = t;
    p = Bbuf + row0 * LDP + kc;
    t.x = f2tf(b0.x); t.y = f2tf(b0.y); t.z = f2tf(b0.z); t.w = f2tf(b0.w);
    *(uint4*)p = t;
    t.x = f2tf(b1.x); t.y = f2tf(b1.y); t.z = f2tf(b1.z); t.w = f2tf(b1.w);
    *(uint4*)(p + 64 * LDP) = t;
}

template <int EPI>
__global__ __launch_bounds__(256) void gemm_kernel(
    const float* __restrict__ A,
    const float* __restrict__ W,
    float* __restrict__ dst)
{
    __shared__ __align__(16) unsigned As[2][BM * LDP];
    __shared__ __align__(16) unsigned Bs[2][BN * LDP];

    const int tid  = threadIdx.x;
    const int lane = tid & 31;
    const int warp = tid >> 5;
    const int wm   = warp & 1;    // 0..1
    const int wn   = warp >> 1;   // 0..3
    const int m0   = blockIdx.y * BM;
    const int n0   = blockIdx.x * BN;

    const int lr = lane >> 2;     // 0..7
    const int lc = lane & 3;      // 0..3

    const int row0 = tid >> 2;           // 0..63
    const int kc   = (tid & 3) * 4;      // 0,4,8,12

    const float* Aptr = A + (m0 + row0) * GK + kc;
    const float* Wptr = W + (n0 + row0) * GK + kc;

    float c[4][4][4];
    #pragma unroll
    for (int i = 0; i < 4; i++)
        #pragma unroll
        for (int j = 0; j < 4; j++)
            #pragma unroll
            for (int r = 0; r < 4; r++)
                c[i][j][r] = 0.f;

    const int NST = GK / BKK;   // 64 stages

    float4 la0 = *(const float4*)Aptr;
    float4 la1 = *(const float4*)(Aptr + 64 * GK);
    float4 lb0 = *(const float4*)Wptr;
    float4 lb1 = *(const float4*)(Wptr + 64 * GK);
    sts_tile(As[0], Bs[0], row0, kc, la0, la1, lb0, lb1);
    __syncthreads();

    for (int s = 0; s < NST; s++) {
        const int cur = s & 1;
        if (s + 1 < NST) {
            const float* ap = Aptr + (s + 1) * BKK;
            const float* wp = Wptr + (s + 1) * BKK;
            la0 = *(const float4*)ap;
            la1 = *(const float4*)(ap + 64 * GK);
            lb0 = *(const float4*)wp;
            lb1 = *(const float4*)(wp + 64 * GK);
        }

        #pragma unroll
        for (int ks = 0; ks < 2; ks++) {
            unsigned af[4][4], bf[4][2];
            #pragma unroll
            for (int mf = 0; mf < 4; mf++) {
                const int m = wm * 64 + mf * 16 + lr;
                const unsigned* p = &As[cur][m * LDP + ks * 8 + lc];
                af[mf][0] = p[0];
                af[mf][1] = p[8 * LDP];
                af[mf][2] = p[4];
                af[mf][3] = p[8 * LDP + 4];
            }
            #pragma unroll
            for (int nf = 0; nf < 4; nf++) {
                const int n = wn * 32 + nf * 8 + lr;
                const unsigned* p = &Bs[cur][n * LDP + ks * 8 + lc];
                bf[nf][0] = p[0];
                bf[nf][1] = p[4];
            }
            #pragma unroll
            for (int mf = 0; mf < 4; mf++)
                #pragma unroll
                for (int nf = 0; nf < 4; nf++)
                    mma_tf32(c[mf][nf], af[mf], bf[nf]);
        }

        if (s + 1 < NST) {
            sts_tile(As[(s + 1) & 1], Bs[(s + 1) & 1], row0, kc, la0, la1, lb0, lb1);
            __syncthreads();
        }
    }

    // Epilogue
    #pragma unroll
    for (int mf = 0; mf < 4; mf++) {
        #pragma unroll
        for (int nf = 0; nf < 4; nf++) {
            const int col = n0 + wn * 32 + nf * 8 + lc * 2;   // even
            #pragma unroll
            for (int half = 0; half < 2; half++) {
                const int r  = m0 + wm * 64 + mf * 16 + lr + half * 8;
                const float v0 = c[mf][nf][half * 2 + 0];
                const float v1 = c[mf][nf][half * 2 + 1];
                if (EPI == 2) {
                    *(float2*)&dst[r * DMODEL + col] = make_float2(v0, v1);
                } else {
                    const int bb = r >> 11;            // / SEQ
                    const int sI = r & (SEQ - 1);
                    const int h  = col >> 6;
                    const int dd = col & 63;           // even
                    const int base = ((bb * NHEADS + h) * SEQ + sI) * DK + dd;
                    if (EPI == 0) {
                        const float cs = g_cos[sI * 32 + (dd >> 1)];
                        const float sn = g_sin[sI * 32 + (dd >> 1)];
                        *(float2*)&dst[base] =
                            make_float2(v0 * cs - v1 * sn, v0 * sn + v1 * cs);
                    } else {
                        *(float2*)&dst[base] = make_float2(v0, v1);
                    }
                }
            }
        }
    }
}

// ---------------------------------------------------------------------------
// Kernel 2: tensor-core flash attention (tf32 mma).
// CTA: 4 warps, 64 queries (16 per warp). Key tiles of 64.
// K,V in smem [key][d] pitch 68 (conflict-free B-frags for QK; ~2-way for PV).
// P round-trips through per-warp smem to convert C-layout -> A-layout.
// ---------------------------------------------------------------------------
#define PIT 68
// smem words: Ks 64*68, Vs 64*68, P 4*16*68  = 13056 words = 52224 bytes
#define ATTN_SMEM_BYTES ((64 * PIT * 2 + 4 * 16 * PIT) * 4)

__global__ __launch_bounds__(128) void attn_mma_kernel()
{
    extern __shared__ unsigned sm[];
    unsigned* Ks = sm;                     // [key][d]
    unsigned* Vs = sm + 64 * PIT;          // [key][d]
    unsigned* Pw = sm + 2 * 64 * PIT + (threadIdx.x >> 5) * 16 * PIT;

    const int tid  = threadIdx.x;
    const int lane = tid & 31;
    const int warp = tid >> 5;
    const int gid  = lane >> 2;   // 0..7
    const int tig  = lane & 3;    // 0..3

    const int h  = blockIdx.y;
    const int b  = blockIdx.z;
    const int qb = gridDim.x - 1 - blockIdx.x;   // heavy blocks first
    const int q0 = qb * 64;

    const float* kbase = g_k + (size_t)((b * NHEADS + h) * SEQ) * DK;
    const float* vbase = g_v + (size_t)((b * NHEADS + h) * SEQ) * DK;
    const float* qbase = g_q + (size_t)((b * NHEADS + h) * SEQ + q0) * DK;

    // Q fragments (scaled by 1/sqrt(64), tf32). Rows warp*16+gid, +8.
    unsigned qf[8][4];
    {
        const int r0 = warp * 16 + gid;
        #pragma unroll
        for (int kc = 0; kc < 8; kc++) {
            qf[kc][0] = f2tf(0.125f * qbase[r0 * 64 + kc * 8 + tig]);
            qf[kc][1] = f2tf(0.125f * qbase[(r0 + 8) * 64 + kc * 8 + tig]);
            qf[kc][2] = f2tf(0.125f * qbase[r0 * 64 + kc * 8 + tig + 4]);
            qf[kc][3] = f2tf(0.125f * qbase[(r0 + 8) * 64 + kc * 8 + tig + 4]);
        }
    }

    float o[8][4];
    #pragma unroll
    for (int nt = 0; nt < 8; nt++)
        #pragma unroll
        for (int r = 0; r < 4; r++)
            o[nt][r] = 0.f;
    float m0v = -1e30f, m1v = -1e30f, l0 = 0.f, l1 = 0.f;

    const int ntiles = qb + 1;
    for (int kt = 0; kt < ntiles; kt++) {
        __syncthreads();   // previous-tile smem reads complete
        #pragma unroll
        for (int i = 0; i < 8; i++) {
            const int idx = i * 128 + tid;
            const int key = idx >> 4;
            const int c4  = (idx & 15) * 4;
            float4 kv = *(const float4*)&kbase[(size_t)(kt * 64 + key) * 64 + c4];
            float4 vv = *(const float4*)&vbase[(size_t)(kt * 64 + key) * 64 + c4];
            uint4 u;
            u.x = f2tf(kv.x); u.y = f2tf(kv.y); u.z = f2tf(kv.z); u.w = f2tf(kv.w);
            *(uint4*)&Ks[key * PIT + c4] = u;
            u.x = f2tf(vv.x); u.y = f2tf(vv.y); u.z = f2tf(vv.z); u.w = f2tf(vv.w);
            *(uint4*)&Vs[key * PIT + c4] = u;
        }
        __syncthreads();

        // S = Q K^T (16 x 64 per warp)
        float s[8][4];
        #pragma unroll
        for (int nt = 0; nt < 8; nt++) {
            s[nt][0] = s[nt][1] = s[nt][2] = s[nt][3] = 0.f;
            #pragma unroll
            for (int kc = 0; kc < 8; kc++) {
                unsigned bf[2];
                const unsigned* p = &Ks[(nt * 8 + gid) * PIT + kc * 8 + tig];
                bf[0] = p[0];
                bf[1] = p[4];
                mma_tf32(s[nt], qf[kc], bf);
            }
        }

        // Causal mask on diagonal tile
        if (kt == qb) {
            const int r0 = warp * 16 + gid;
            #pragma unroll
            for (int nt = 0; nt < 8; nt++) {
                const int c = nt * 8 + 2 * tig;
                if (c > r0)         s[nt][0] = -1e30f;
                if (c + 1 > r0)     s[nt][1] = -1e30f;
                if (c > r0 + 8)     s[nt][2] = -1e30f;
                if (c + 1 > r0 + 8) s[nt][3] = -1e30f;
            }
        }

        // Row max (rows lr and lr+8)
        float mx0 = -1e30f, mx1 = -1e30f;
        #pragma unroll
        for (int nt = 0; nt < 8; nt++) {
            mx0 = fmaxf(mx0, fmaxf(s[nt][0], s[nt][1]));
            mx1 = fmaxf(mx1, fmaxf(s[nt][2], s[nt][3]));
        }
        mx0 = fmaxf(mx0, __shfl_xor_sync(0xffffffffu, mx0, 1));
        mx0 = fmaxf(mx0, __shfl_xor_sync(0xffffffffu, mx0, 2));
        mx1 = fmaxf(mx1, __shfl_xor_sync(0xffffffffu, mx1, 1));
        mx1 = fmaxf(mx1, __shfl_xor_sync(0xffffffffu, mx1, 2));

        const float nm0 = fmaxf(m0v, mx0);
        const float nm1 = fmaxf(m1v, mx1);
        const float al0 = __expf(m0v - nm0);
        const float al1 = __expf(m1v - nm1);
        m0v = nm0; m1v = nm1;

        // p = exp(s - m); write to P smem (tf32); accumulate row sums
        float rs0 = 0.f, rs1 = 0.f;
        #pragma unroll
        for (int nt = 0; nt < 8; nt++) {
            const float p0 = __expf(s[nt][0] - m0v);
            const float p1 = __expf(s[nt][1] - m0v);
            const float p2 = __expf(s[nt][2] - m1v);
            const float p3 = __expf(s[nt][3] - m1v);
            rs0 += p0 + p1;
            rs1 += p2 + p3;
            uint2 w0; w0.x = f2tf(p0); w0.y = f2tf(p1);
            uint2 w1; w1.x = f2tf(p2); w1.y = f2tf(p3);
            *(uint2*)&Pw[gid * PIT + nt * 8 + 2 * tig]       = w0;
            *(uint2*)&Pw[(gid + 8) * PIT + nt * 8 + 2 * tig] = w1;
        }
        rs0 += __shfl_xor_sync(0xffffffffu, rs0, 1);
        rs0 += __shfl_xor_sync(0xffffffffu, rs0, 2);
        rs1 += __shfl_xor_sync(0xffffffffu, rs1, 1);
        rs1 += __shfl_xor_sync(0xffffffffu, rs1, 2);
        l0 = l0 * al0 + rs0;
        l1 = l1 * al1 + rs1;

        // Rescale O
        #pragma unroll
        for (int nt = 0; nt < 8; nt++) {
            o[nt][0] *= al0; o[nt][1] *= al0;
            o[nt][2] *= al1; o[nt][3] *= al1;
        }

        __syncwarp();   // P visible across lanes

        // O += P @ V
        #pragma unroll
        for (int kc = 0; kc < 8; kc++) {
            unsigned af[4];
            af[0] = Pw[gid * PIT + kc * 8 + tig];
            af[1] = Pw[(gid + 8) * PIT + kc * 8 + tig];
            af[2] = Pw[gid * PIT + kc * 8 + tig + 4];
            af[3] = Pw[(gid + 8) * PIT + kc * 8 + tig + 4];
            #pragma unroll
            for (int nt = 0; nt < 8; nt++) {
                unsigned bf[2];
                const unsigned* p = &Vs[(kc * 8 + tig) * PIT + nt * 8 + gid];
                bf[0] = p[0];
                bf[1] = p[4 * PIT];
                mma_tf32(o[nt], af, bf);
            }
        }
    }

    // Epilogue: O /= l, scatter to ctx [b*S+q][h*64+d]
    const float il0 = 1.0f / l0;
    const float il1 = 1.0f / l1;
    float* ob = g_ctx + (size_t)(b * SEQ + q0 + warp * 16) * DMODEL + h * 64;
    #pragma unroll
    for (int nt = 0; nt < 8; nt++) {
        const int col = nt * 8 + 2 * tig;
        *(float2*)&ob[gid * DMODEL + col] =
            make_float2(o[nt][0] * il0, o[nt][1] * il0);
        *(float2*)&ob[(gid + 8) * DMODEL + col] =
            make_float2(o[nt][2] * il1, o[nt][3] * il1);
    }
}

// ---------------------------------------------------------------------------
extern "C" void kernel_launch(void* const* d_in, const int* in_sizes, int n_in,
                              void* d_out, int out_size)
{
    const float* x  = (const float*)d_in[0];
    const float* Wq = (const float*)d_in[1];
    const float* Wk = (const float*)d_in[2];
    const float* Wv = (const float*)d_in[3];
    const float* Wo = (const float*)d_in[4];
    float* out = (float*)d_out;

    float* q_p;   cudaGetSymbolAddress((void**)&q_p,   g_q);
    float* k_p;   cudaGetSymbolAddress((void**)&k_p,   g_k);
    float* v_p;   cudaGetSymbolAddress((void**)&v_p,   g_v);
    float* ctx_p; cudaGetSymbolAddress((void**)&ctx_p, g_ctx);

    cudaFuncSetAttribute(attn_mma_kernel,
                         cudaFuncAttributeMaxDynamicSharedMemorySize,
                         ATTN_SMEM_BYTES);

    rope_table_kernel<<<256, 256>>>();

    dim3 gg(DMODEL / BN, NQ / BM);
    gemm_kernel<0><<<gg, 256>>>(x, Wq, q_p);
    gemm_kernel<0><<<gg, 256>>>(x, Wk, k_p);
    gemm_kernel<1><<<gg, 256>>>(x, Wv, v_p);

    dim3 ga(SEQ / 64, NHEADS, BATCH);
    attn_mma_kernel<<<ga, 128, ATTN_SMEM_BYTES>>>();

    gemm_kernel<2><<<gg, 256>>>(ctx_p, Wo, out);
}